// round 8
// baseline (speedup 1.0000x reference)
#include <cuda_runtime.h>
#include <cstdint>
#include <math.h>

#define BB 64
#define HH 256
#define WW 256
#define HWSZ 65536           // H*W
#define NTOT 4194304         // B*H*W

// Output layout (concatenated, reference return order):
#define OFF_UIFFT 0
#define OFF_ABS   8388608
#define OFF_MASK  12582912
#define OFF_FFT   16777216
#define OFF_UK    25165824

__device__ double g_partial[64];
__device__ float  g_r, g_beta;
__device__ int    g_le;
__device__ float  g_prob2[HWSZ];   // rescaled probability map
// lane-major twiddle tables [b][r][lane], lo-lane = (1,0) baked in
__device__ float g_tab_fr[1280], g_tab_fi[1280];   // forward
__device__ float g_tab_ir[1280], g_tab_ii[1280];   // inverse

// ---------------- Threefry-2x32-20 (exact jax) ----------------
__host__ __device__ __forceinline__ unsigned rotl32(unsigned v, int d) {
    return (v << d) | (v >> (32 - d));
}

__host__ __device__ __forceinline__ void threefry2x32(unsigned k0, unsigned k1,
                                                      unsigned c0, unsigned c1,
                                                      unsigned& o0, unsigned& o1) {
    unsigned ks2 = k0 ^ k1 ^ 0x1BD11BDAu;
    unsigned x0 = c0 + k0;
    unsigned x1 = c1 + k1;
#define TF_R(r) { x0 += x1; x1 = rotl32(x1, r); x1 ^= x0; }
    TF_R(13) TF_R(15) TF_R(26) TF_R(6)
    x0 += k1;  x1 += ks2 + 1u;
    TF_R(17) TF_R(29) TF_R(16) TF_R(24)
    x0 += ks2; x1 += k0 + 2u;
    TF_R(13) TF_R(15) TF_R(26) TF_R(6)
    x0 += k0;  x1 += k1 + 3u;
    TF_R(17) TF_R(29) TF_R(16) TF_R(24)
    x0 += k1;  x1 += ks2 + 4u;
    TF_R(13) TF_R(15) TF_R(26) TF_R(6)
    x0 += ks2; x1 += k0 + 5u;
#undef TF_R
    o0 = x0; o1 = x1;
}

// ---------------- XLA-exact sigmoid pieces ----------------
__device__ __forceinline__ float tanh_xla(float x) {
    float ax = fabsf(x);
    float xc = fminf(fmaxf(x, -7.90531110763549805f), 7.90531110763549805f);
    float x2 = __fmul_rn(xc, xc);
    float p = -2.76076847742355e-16f;
    p = fmaf(p, x2, 2.00018790482477e-13f);
    p = fmaf(p, x2, -8.60467152213735e-11f);
    p = fmaf(p, x2, 5.12229709037114e-08f);
    p = fmaf(p, x2, 1.48572235717979e-05f);
    p = fmaf(p, x2, 6.37261928875436e-04f);
    p = fmaf(p, x2, 4.89352455891786e-03f);
    p = __fmul_rn(p, xc);
    float q = 1.19825839466702e-06f;
    q = fmaf(q, x2, 1.18534705686654e-04f);
    q = fmaf(q, x2, 2.26843463243900e-03f);
    q = fmaf(q, x2, 4.89352518554385e-03f);
    float r = __fdiv_rn(p, q);
    return (ax < 0.0004f) ? x : r;
}

__device__ __forceinline__ float prob1_of(float wv) {
    float arg = __fmul_rn(0.5f, __fmul_rn(5.0f, wv));
    float t = tanh_xla(arg);
    return __fadd_rn(0.5f, __fmul_rn(0.5f, t));
}

// ---------------- reduction: xbar = mean(prob1) over H*W ----------------
__global__ void k_reduce(const float* __restrict__ w) {
    __shared__ double sd[256];
    int t = threadIdx.x;
    int i0 = (blockIdx.x * 256 + t) * 4;
    float4 wq = *reinterpret_cast<const float4*>(w + i0);
    sd[t] = (double)prob1_of(wq.x) + (double)prob1_of(wq.y)
          + (double)prob1_of(wq.z) + (double)prob1_of(wq.w);
    __syncthreads();
    for (int s = 128; s > 0; s >>= 1) {
        if (t < s) sd[t] += sd[t + s];
        __syncthreads();
    }
    if (t == 0) g_partial[blockIdx.x] = sd[0];
}

// final sum + constants + lane-major twiddle tables
__global__ void k_final() {
    __shared__ double sd[64];
    int t = threadIdx.x;
    if (t < 64) sd[t] = g_partial[t];
    for (int idx = t; idx < 1280; idx += 256) {
        int b = idx >> 8;
        int r = (idx >> 5) & 7;
        int lane = idx & 31;
        int M = 1 << b;
        float re = 1.0f, im = 0.0f;
        if ((lane >> b) & 1) {
            int k = (((lane & (M - 1)) * 8) + r) << (4 - b);
            float s, c;
            sincospif((float)k / 128.0f, &s, &c);
            re = c; im = -s;
        }
        g_tab_fr[idx] = re; g_tab_fi[idx] = im;
        g_tab_ir[idx] = re; g_tab_ii[idx] = -im;
    }
    __syncthreads();
    for (int s = 32; s > 0; s >>= 1) {
        if (t < s) sd[t] += sd[t + s];
        __syncthreads();
    }
    if (t == 0) {
        float xbar = (float)(sd[0] / 65536.0);
        g_r    = __fdiv_rn(0.125f, xbar);
        g_beta = __fdiv_rn(0.875f, __fsub_rn(1.0f, xbar));
        g_le   = (g_r < 1.0f) ? 1 : 0;
    }
}

// ---------------- register warp FFT (256-pt, 8 regs x 32 lanes) ----------
__device__ __constant__ int BREV3[8] = {0, 4, 2, 6, 1, 5, 3, 7};
#define SWZ(row) ((row) ^ ((row) >> 5))
#define HSQ 0.70710678118654752f

// smem-table variant: twr/twi point to a 1280-float smem copy for this direction
template<int SIGN>   // -1 fwd, +1 inv
__device__ __forceinline__ void wfft(float (&vr)[8], float (&vi)[8], int lane,
                                     const float* __restrict__ twr,
                                     const float* __restrict__ twi) {
#pragma unroll
    for (int a = 0; a < 8; a += 2) {
        float tr = vr[a + 1], ti = vi[a + 1];
        vr[a + 1] = vr[a] - tr; vi[a + 1] = vi[a] - ti;
        vr[a] += tr; vi[a] += ti;
    }
#pragma unroll
    for (int a0 = 0; a0 < 8; a0 += 4) {
        { int a = a0, b = a0 + 2;
          float tr = vr[b], ti = vi[b];
          vr[b] = vr[a] - tr; vi[b] = vi[a] - ti; vr[a] += tr; vi[a] += ti; }
        { int a = a0 + 1, b = a0 + 3;
          float tr = (SIGN > 0) ? -vi[b] : vi[b];
          float ti = (SIGN > 0) ?  vr[b] : -vr[b];
          vr[b] = vr[a] - tr; vi[b] = vi[a] - ti; vr[a] += tr; vi[a] += ti; }
    }
    {
        { int a = 0, b = 4;
          float tr = vr[b], ti = vi[b];
          vr[b] = vr[a] - tr; vi[b] = vi[a] - ti; vr[a] += tr; vi[a] += ti; }
        { int a = 1, b = 5;
          float xr = vr[b], xi = vi[b];
          float tr = HSQ * (SIGN > 0 ? (xr - xi) : (xr + xi));
          float ti = HSQ * (SIGN > 0 ? (xi + xr) : (xi - xr));
          vr[b] = vr[a] - tr; vi[b] = vi[a] - ti; vr[a] += tr; vi[a] += ti; }
        { int a = 2, b = 6;
          float xr = vr[b], xi = vi[b];
          float tr = (SIGN > 0) ? -xi : xi;
          float ti = (SIGN > 0) ?  xr : -xr;
          vr[b] = vr[a] - tr; vi[b] = vi[a] - ti; vr[a] += tr; vi[a] += ti; }
        { int a = 3, b = 7;
          float xr = vr[b], xi = vi[b];
          float tr = -HSQ * (SIGN > 0 ? (xr + xi) : (xr - xi));
          float ti =  HSQ * (SIGN > 0 ? (xr - xi) : -(xr + xi));
          vr[b] = vr[a] - tr; vi[b] = vi[a] - ti; vr[a] += tr; vi[a] += ti; }
    }
#pragma unroll
    for (int b = 0; b < 5; b++) {
        int M = 1 << b;
        unsigned hib = (lane >> b) & 1u;
        float s = 1.0f - 2.0f * (float)hib;
        const float* br_ = twr + b * 256 + lane;
        const float* bi_ = twi + b * 256 + lane;
#pragma unroll
        for (int r = 0; r < 8; r++) {
            float wr = br_[r * 32];
            float wi = bi_[r * 32];
            float zr = wr * vr[r] - wi * vi[r];
            float zi = wr * vi[r] + wi * vr[r];
            float pr = __shfl_xor_sync(0xffffffffu, zr, M);
            float pi = __shfl_xor_sync(0xffffffffu, zi, M);
            vr[r] = fmaf(s, zr, pr);
            vi[r] = fmaf(s, zi, pi);
        }
    }
}

// ---------------- row forward FFT + prob2-table CTAs ----------------
__global__ void k_row_fwd(const float* __restrict__ x, float* __restrict__ fftreg,
                          const float* __restrict__ w) {
    if (blockIdx.x == HH / 8) {
        int idx0 = blockIdx.y * 1024 + threadIdx.x * 4;
        float4 wq = *reinterpret_cast<const float4*>(w + idx0);
        float rr = g_r, bb = g_beta;
        int le = g_le;
        float pv[4] = {wq.x, wq.y, wq.z, wq.w};
        float res[4];
#pragma unroll
        for (int j = 0; j < 4; j++) {
            float p1 = prob1_of(pv[j]);
            res[j] = le ? __fmul_rn(p1, rr)
                        : __fsub_rn(1.0f, __fmul_rn(__fsub_rn(1.0f, p1), bb));
        }
        *reinterpret_cast<float4*>(g_prob2 + idx0) = make_float4(res[0], res[1], res[2], res[3]);
        return;
    }
    __shared__ float sr[8][256], si[8][256];
    __shared__ float s_twr[1280], s_twi[1280];
    int t = threadIdx.x, lane = t & 31, wp = t >> 5;
    for (int i = t; i < 1280; i += 256) { s_twr[i] = g_tab_fr[i]; s_twi[i] = g_tab_fi[i]; }
    __syncthreads();
    int row = blockIdx.x * 8 + wp, b = blockIdx.y;
    int b5 = __brev(lane) >> 27;
    const float* xp = x + (size_t)b * HWSZ + (size_t)row * WW;
    float vr[8], vi[8];
#pragma unroll
    for (int r = 0; r < 8; r++) { vr[r] = xp[BREV3[r] * 32 + b5]; vi[r] = 0.0f; }
    wfft<-1>(vr, vi, lane, s_twr, s_twi);
#pragma unroll
    for (int r = 0; r < 8; r++) {
        int p = lane * 8 + r, a = SWZ(p);
        sr[wp][a] = vr[r]; si[wp][a] = vi[r];
    }
    __syncwarp();
    float* fr = fftreg + (size_t)b * 2 * HWSZ + (size_t)row * WW;
    float* fi = fr + HWSZ;
#pragma unroll
    for (int k = 0; k < 2; k++) {
        int p0 = (k * 32 + lane) * 4;
        float4 vre, vim;
        vre.x = sr[wp][SWZ(p0)];     vim.x = si[wp][SWZ(p0)];
        vre.y = sr[wp][SWZ(p0 + 1)]; vim.y = si[wp][SWZ(p0 + 1)];
        vre.z = sr[wp][SWZ(p0 + 2)]; vim.z = si[wp][SWZ(p0 + 2)];
        vre.w = sr[wp][SWZ(p0 + 3)]; vim.w = si[wp][SWZ(p0 + 3)];
        *reinterpret_cast<float4*>(fr + p0) = vre;
        *reinterpret_cast<float4*>(fi + p0) = vim;
    }
}

// ---------- fused column kernel: 32-col tile, 512 threads, smem twiddles ----------
#define CCP 288
#define SMADDR(col, row) ((col) * CCP + (SWZ(row) ^ ((((col) >> 2) & 7) << 2)))

__global__ void __launch_bounds__(512, 2)
k_col(float* __restrict__ fftreg, float* __restrict__ maskreg,
      float* __restrict__ ukreg, float* __restrict__ stage,
      unsigned sk0, unsigned sk1) {
    extern __shared__ float sm[];
    float* sre = sm;
    float* sim = sm + 32 * CCP;
    float* s_fr = sm + 64 * CCP;
    float* s_fi = s_fr + 1280;
    float* s_ir = s_fi + 1280;
    float* s_ii = s_ir + 1280;
    int t = threadIdx.x, lane = t & 31, wp = t >> 5;   // wp 0..15
    int b = blockIdx.y, c0 = blockIdx.x * 32;
    int cg = t & 7, rloc = t >> 3;                     // rloc 0..63
    int b5 = __brev(lane) >> 27;
    float* fr = fftreg + (size_t)b * 2 * HWSZ;
    float* fi = fr + HWSZ;

    // stage twiddle tables (both directions)
    for (int i = t; i < 1280; i += 512) {
        s_fr[i] = g_tab_fr[i]; s_fi[i] = g_tab_fi[i];
        s_ir[i] = g_tab_ir[i]; s_ii[i] = g_tab_ii[i];
    }

    // load 256x32 tile, float4 (fully coalesced)
#pragma unroll
    for (int k = 0; k < 4; k++) {
        int row = k * 64 + rloc;
        int g = row * WW + c0 + cg * 4;
        float4 vre = *reinterpret_cast<const float4*>(fr + g);
        float4 vim = *reinterpret_cast<const float4*>(fi + g);
        int c = cg * 4;
        sre[SMADDR(c, row)] = vre.x;     sim[SMADDR(c, row)] = vim.x;
        sre[SMADDR(c + 1, row)] = vre.y; sim[SMADDR(c + 1, row)] = vim.y;
        sre[SMADDR(c + 2, row)] = vre.z; sim[SMADDR(c + 2, row)] = vim.z;
        sre[SMADDR(c + 3, row)] = vre.w; sim[SMADDR(c + 3, row)] = vim.w;
    }
    __syncthreads();

    // forward FFTs: 2 columns per warp, sequential
#pragma unroll 1
    for (int j = 0; j < 2; j++) {
        int cc = wp * 2 + j;
        float vr[8], vi[8];
#pragma unroll
        for (int r = 0; r < 8; r++) {
            int ri = BREV3[r] * 32 + b5;
            vr[r] = sre[SMADDR(cc, ri)]; vi[r] = sim[SMADDR(cc, ri)];
        }
        wfft<-1>(vr, vi, lane, s_fr, s_fi);
        __syncwarp();
#pragma unroll
        for (int r = 0; r < 8; r++) {
            int p = lane * 8 + r;
            sre[SMADDR(cc, p)] = vr[r]; sim[SMADDR(cc, p)] = vi[r];
        }
        __syncwarp();
    }
    __syncthreads();

    // outputs: fft, mask (threefry), u_k (float4); stash u_k in smem
    float* ur = ukreg + (size_t)b * 2 * HWSZ;
    float* ui = ur + HWSZ;
    float* mk = maskreg + (size_t)b * HWSZ;
#pragma unroll 1
    for (int k = 0; k < 4; k++) {
        int row = k * 64 + rloc;
        int g = row * WW + c0 + cg * 4;
        int c = cg * 4;
        float xr[4], xi[4], mm[4];
        unsigned base = (unsigned)(b * HWSZ + g);
        float4 p2 = *reinterpret_cast<const float4*>(g_prob2 + g);
        float pv[4] = {p2.x, p2.y, p2.z, p2.w};
#pragma unroll
        for (int q = 0; q < 4; q++) {
            xr[q] = sre[SMADDR(c + q, row)];
            xi[q] = sim[SMADDR(c + q, row)];
            unsigned o0, o1;
            threefry2x32(sk0, sk1, 0u, base + (unsigned)q, o0, o1);
            unsigned bits = o0 ^ o1;
            float u = __uint_as_float((bits >> 9) | 0x3f800000u) - 1.0f;
            mm[q] = (pv[q] > u) ? 1.0f : 0.0f;
        }
        *reinterpret_cast<float4*>(fr + g) = make_float4(xr[0], xr[1], xr[2], xr[3]);
        *reinterpret_cast<float4*>(fi + g) = make_float4(xi[0], xi[1], xi[2], xi[3]);
        *reinterpret_cast<float4*>(mk + g) = make_float4(mm[0], mm[1], mm[2], mm[3]);
        float kr[4], ki[4];
#pragma unroll
        for (int q = 0; q < 4; q++) {
            kr[q] = xr[q] * mm[q]; ki[q] = xi[q] * mm[q];
            sre[SMADDR(c + q, row)] = kr[q];
            sim[SMADDR(c + q, row)] = ki[q];
        }
        *reinterpret_cast<float4*>(ur + g) = make_float4(kr[0], kr[1], kr[2], kr[3]);
        *reinterpret_cast<float4*>(ui + g) = make_float4(ki[0], ki[1], ki[2], ki[3]);
    }
    __syncthreads();

    // inverse FFTs: 2 columns per warp, scale 1/256
#pragma unroll 1
    for (int j = 0; j < 2; j++) {
        int cc = wp * 2 + j;
        float vr[8], vi[8];
#pragma unroll
        for (int r = 0; r < 8; r++) {
            int ri = BREV3[r] * 32 + b5;
            vr[r] = sre[SMADDR(cc, ri)]; vi[r] = sim[SMADDR(cc, ri)];
        }
        wfft<1>(vr, vi, lane, s_ir, s_ii);
        __syncwarp();
        const float sc = 1.0f / 256.0f;
#pragma unroll
        for (int r = 0; r < 8; r++) {
            int p = lane * 8 + r;
            sre[SMADDR(cc, p)] = vr[r] * sc; sim[SMADDR(cc, p)] = vi[r] * sc;
        }
        __syncwarp();
    }
    __syncthreads();

    // store to staging (uifft region), float4
    float* dr = stage + (size_t)b * 2 * HWSZ;
    float* di = dr + HWSZ;
#pragma unroll
    for (int k = 0; k < 4; k++) {
        int row = k * 64 + rloc;
        int g = row * WW + c0 + cg * 4;
        int c = cg * 4;
        float4 vre, vim;
        vre.x = sre[SMADDR(c, row)];     vim.x = sim[SMADDR(c, row)];
        vre.y = sre[SMADDR(c + 1, row)]; vim.y = sim[SMADDR(c + 1, row)];
        vre.z = sre[SMADDR(c + 2, row)]; vim.z = sim[SMADDR(c + 2, row)];
        vre.w = sre[SMADDR(c + 3, row)]; vim.w = sim[SMADDR(c + 3, row)];
        *reinterpret_cast<float4*>(dr + g) = vre;
        *reinterpret_cast<float4*>(di + g) = vim;
    }
}

// ---------- row inverse FFT (in place on uifft) + complex abs ----------
__global__ void k_row_inv(float* __restrict__ uifft, float* __restrict__ cabs) {
    __shared__ float sr[8][256], si[8][256];
    __shared__ float s_twr[1280], s_twi[1280];
    int t = threadIdx.x, lane = t & 31, wp = t >> 5;
    for (int i = t; i < 1280; i += 256) { s_twr[i] = g_tab_ir[i]; s_twi[i] = g_tab_ii[i]; }
    __syncthreads();
    int row = blockIdx.x * 8 + wp, b = blockIdx.y;
    int b5 = __brev(lane) >> 27;
    float* fr = uifft + (size_t)b * 2 * HWSZ + (size_t)row * WW;
    float* fi = fr + HWSZ;
    float vr[8], vi[8];
#pragma unroll
    for (int r = 0; r < 8; r++) {
        int p = BREV3[r] * 32 + b5;
        vr[r] = fr[p]; vi[r] = fi[p];
    }
    wfft<1>(vr, vi, lane, s_twr, s_twi);
    const float sc = 1.0f / 256.0f;
#pragma unroll
    for (int r = 0; r < 8; r++) {
        int p = lane * 8 + r, a = SWZ(p);
        sr[wp][a] = vr[r] * sc; si[wp][a] = vi[r] * sc;
    }
    __syncwarp();
    float* ap = cabs + (size_t)b * HWSZ + (size_t)row * WW;
#pragma unroll
    for (int k = 0; k < 2; k++) {
        int p0 = (k * 32 + lane) * 4;
        float4 vre, vim, va;
        vre.x = sr[wp][SWZ(p0)];     vim.x = si[wp][SWZ(p0)];
        vre.y = sr[wp][SWZ(p0 + 1)]; vim.y = si[wp][SWZ(p0 + 1)];
        vre.z = sr[wp][SWZ(p0 + 2)]; vim.z = si[wp][SWZ(p0 + 2)];
        vre.w = sr[wp][SWZ(p0 + 3)]; vim.w = si[wp][SWZ(p0 + 3)];
        va.x = sqrtf(vre.x * vre.x + vim.x * vim.x);
        va.y = sqrtf(vre.y * vre.y + vim.y * vim.y);
        va.z = sqrtf(vre.z * vre.z + vim.z * vim.z);
        va.w = sqrtf(vre.w * vre.w + vim.w * vim.w);
        *reinterpret_cast<float4*>(fr + p0) = vre;
        *reinterpret_cast<float4*>(fi + p0) = vim;
        *reinterpret_cast<float4*>(ap + p0) = va;
    }
}

extern "C" void kernel_launch(void* const* d_in, const int* in_sizes, int n_in,
                              void* d_out, int out_size) {
    const float* x = (const float*)d_in[0];
    const float* w = (const float*)d_in[1];
    if (n_in >= 2 && in_sizes[0] == HWSZ) {
        x = (const float*)d_in[1];
        w = (const float*)d_in[0];
    }
    float* out   = (float*)d_out;
    float* uifft = out + OFF_UIFFT;
    float* cabs  = out + OFF_ABS;
    float* mask  = out + OFF_MASK;
    float* fft   = out + OFF_FFT;
    float* uk    = out + OFF_UK;

    unsigned sk0, sk1;
    threefry2x32(0u, 42u, 0u, 1u, sk0, sk1);

    const int col_smem = (2 * 32 * CCP + 4 * 1280) * (int)sizeof(float);   // 94208
    static int smem_set = 0;
    if (!smem_set) {
        cudaFuncSetAttribute(k_col, cudaFuncAttributeMaxDynamicSharedMemorySize, col_smem);
        smem_set = 1;
    }

    k_reduce<<<64, 256>>>(w);
    k_final<<<1, 256>>>();
    k_row_fwd<<<dim3(HH / 8 + 1, BB), 256>>>(x, fft, w);
    k_col<<<dim3(WW / 32, BB), 512, col_smem>>>(fft, mask, uk, uifft, sk0, sk1);
    k_row_inv<<<dim3(HH / 8, BB), 256>>>(uifft, cabs);
}

// round 9
// speedup vs baseline: 1.2464x; 1.2464x over previous
#include <cuda_runtime.h>
#include <cstdint>
#include <math.h>

#define BB 64
#define HH 256
#define WW 256
#define HWSZ 65536           // H*W
#define NTOT 4194304         // B*H*W

// Output layout (concatenated, reference return order):
#define OFF_UIFFT 0
#define OFF_ABS   8388608
#define OFF_MASK  12582912
#define OFF_FFT   16777216
#define OFF_UK    25165824

__device__ double g_partial[64];
__device__ float  g_r, g_beta;
__device__ int    g_le;
__device__ float  g_prob2[HWSZ];   // rescaled probability map
// four-step FFT twiddle tables, lane-major [digit*32 + lane]
__device__ float g_t1r_f[256], g_t1i_f[256], g_t1r_i[256], g_t1i_i[256];
__device__ float g_t2r_f[256], g_t2i_f[256], g_t2r_i[256], g_t2i_i[256];

// ---------------- Threefry-2x32-20 (exact jax) ----------------
__host__ __device__ __forceinline__ unsigned rotl32(unsigned v, int d) {
    return (v << d) | (v >> (32 - d));
}

__host__ __device__ __forceinline__ void threefry2x32(unsigned k0, unsigned k1,
                                                      unsigned c0, unsigned c1,
                                                      unsigned& o0, unsigned& o1) {
    unsigned ks2 = k0 ^ k1 ^ 0x1BD11BDAu;
    unsigned x0 = c0 + k0;
    unsigned x1 = c1 + k1;
#define TF_R(r) { x0 += x1; x1 = rotl32(x1, r); x1 ^= x0; }
    TF_R(13) TF_R(15) TF_R(26) TF_R(6)
    x0 += k1;  x1 += ks2 + 1u;
    TF_R(17) TF_R(29) TF_R(16) TF_R(24)
    x0 += ks2; x1 += k0 + 2u;
    TF_R(13) TF_R(15) TF_R(26) TF_R(6)
    x0 += k0;  x1 += k1 + 3u;
    TF_R(17) TF_R(29) TF_R(16) TF_R(24)
    x0 += k1;  x1 += ks2 + 4u;
    TF_R(13) TF_R(15) TF_R(26) TF_R(6)
    x0 += ks2; x1 += k0 + 5u;
#undef TF_R
    o0 = x0; o1 = x1;
}

// ---------------- XLA-exact sigmoid pieces ----------------
__device__ __forceinline__ float tanh_xla(float x) {
    float ax = fabsf(x);
    float xc = fminf(fmaxf(x, -7.90531110763549805f), 7.90531110763549805f);
    float x2 = __fmul_rn(xc, xc);
    float p = -2.76076847742355e-16f;
    p = fmaf(p, x2, 2.00018790482477e-13f);
    p = fmaf(p, x2, -8.60467152213735e-11f);
    p = fmaf(p, x2, 5.12229709037114e-08f);
    p = fmaf(p, x2, 1.48572235717979e-05f);
    p = fmaf(p, x2, 6.37261928875436e-04f);
    p = fmaf(p, x2, 4.89352455891786e-03f);
    p = __fmul_rn(p, xc);
    float q = 1.19825839466702e-06f;
    q = fmaf(q, x2, 1.18534705686654e-04f);
    q = fmaf(q, x2, 2.26843463243900e-03f);
    q = fmaf(q, x2, 4.89352518554385e-03f);
    float r = __fdiv_rn(p, q);
    return (ax < 0.0004f) ? x : r;
}

__device__ __forceinline__ float prob1_of(float wv) {
    float arg = __fmul_rn(0.5f, __fmul_rn(5.0f, wv));
    float t = tanh_xla(arg);
    return __fadd_rn(0.5f, __fmul_rn(0.5f, t));
}

// ---------------- reduction: xbar = mean(prob1) over H*W ----------------
__global__ void k_reduce(const float* __restrict__ w) {
    __shared__ double sd[256];
    int t = threadIdx.x;
    int i0 = (blockIdx.x * 256 + t) * 4;
    float4 wq = *reinterpret_cast<const float4*>(w + i0);
    sd[t] = (double)prob1_of(wq.x) + (double)prob1_of(wq.y)
          + (double)prob1_of(wq.z) + (double)prob1_of(wq.w);
    __syncthreads();
    for (int s = 128; s > 0; s >>= 1) {
        if (t < s) sd[t] += sd[t + s];
        __syncthreads();
    }
    if (t == 0) g_partial[blockIdx.x] = sd[0];
}

// final sum + constants + four-step twiddle tables
__global__ void k_final() {
    __shared__ double sd[64];
    int t = threadIdx.x;
    if (t < 64) sd[t] = g_partial[t];
    {
        int c = t >> 5, l = t & 31;
        float s1, c1;
        sincospif((float)(l * c) / 128.0f, &s1, &c1);   // omega256^{l*c}
        g_t1r_f[t] = c1; g_t1i_f[t] = -s1;
        g_t1r_i[t] = c1; g_t1i_i[t] = s1;
        int d0 = ((l >> 4) & 1) + (((l >> 3) & 1) << 1);
        float s2, c2;
        sincospif((float)(c * d0) / 16.0f, &s2, &c2);   // omega32^{r*e0}
        g_t2r_f[t] = c2; g_t2i_f[t] = -s2;
        const float sc = 1.0f / 256.0f;                 // fold ifft scale into inv tw2
        g_t2r_i[t] = c2 * sc; g_t2i_i[t] = s2 * sc;
    }
    __syncthreads();
    for (int s = 32; s > 0; s >>= 1) {
        if (t < s) sd[t] += sd[t + s];
        __syncthreads();
    }
    if (t == 0) {
        float xbar = (float)(sd[0] / 65536.0);
        g_r    = __fdiv_rn(0.125f, xbar);
        g_beta = __fdiv_rn(0.875f, __fsub_rn(1.0f, xbar));
        g_le   = (g_r < 1.0f) ? 1 : 0;
    }
}

// ---------------- four-step register FFT pieces ----------------
#define SWZ(row) ((row) ^ ((row) >> 5))
#define HSQ 0.70710678118654752f

// 8-pt DIF DFT in registers; input natural order, output reg j = X[brev3(j)]
template<int SIGN>   // omega = e^{2*pi*i*SIGN/8}
__device__ __forceinline__ void radix8(float (&vr)[8], float (&vi)[8]) {
    const float E = (float)SIGN;
    float tr, ti;
    // stage 1 (dist 4), twiddles w8^n on the diff branch
    tr=vr[0]-vr[4]; ti=vi[0]-vi[4]; vr[0]+=vr[4]; vi[0]+=vi[4]; vr[4]=tr; vi[4]=ti;
    tr=vr[1]-vr[5]; ti=vi[1]-vi[5]; vr[1]+=vr[5]; vi[1]+=vi[5];
    vr[5]=HSQ*(tr - E*ti); vi[5]=HSQ*(ti + E*tr);
    tr=vr[2]-vr[6]; ti=vi[2]-vi[6]; vr[2]+=vr[6]; vi[2]+=vi[6];
    vr[6]=-E*ti; vi[6]=E*tr;
    tr=vr[3]-vr[7]; ti=vi[3]-vi[7]; vr[3]+=vr[7]; vi[3]+=vi[7];
    vr[7]=-HSQ*(tr + E*ti); vi[7]=HSQ*(E*tr - ti);
    // stage 2 (dist 2), twiddles w4^n
    tr=vr[0]-vr[2]; ti=vi[0]-vi[2]; vr[0]+=vr[2]; vi[0]+=vi[2]; vr[2]=tr; vi[2]=ti;
    tr=vr[1]-vr[3]; ti=vi[1]-vi[3]; vr[1]+=vr[3]; vi[1]+=vi[3]; vr[3]=-E*ti; vi[3]=E*tr;
    tr=vr[4]-vr[6]; ti=vi[4]-vi[6]; vr[4]+=vr[6]; vi[4]+=vi[6]; vr[6]=tr; vi[6]=ti;
    tr=vr[5]-vr[7]; ti=vi[5]-vi[7]; vr[5]+=vr[7]; vi[5]+=vi[7]; vr[7]=-E*ti; vi[7]=E*tr;
    // stage 3 (dist 1)
    tr=vr[0]-vr[1]; ti=vi[0]-vi[1]; vr[0]+=vr[1]; vi[0]+=vi[1]; vr[1]=tr; vi[1]=ti;
    tr=vr[2]-vr[3]; ti=vi[2]-vi[3]; vr[2]+=vr[3]; vi[2]+=vi[3]; vr[3]=tr; vi[3]=ti;
    tr=vr[4]-vr[5]; ti=vi[4]-vi[5]; vr[4]+=vr[5]; vi[4]+=vi[5]; vr[5]=tr; vi[5]=ti;
    tr=vr[6]-vr[7]; ti=vi[6]-vi[7]; vr[6]+=vr[7]; vi[6]+=vi[7]; vr[7]=tr; vi[7]=ti;
}

// 4-pt DIF DFT across lane bits 3 (b2 low) / 4 (b2 high); output e0 = bit4 + 2*bit3
template<int SIGN>
__device__ __forceinline__ void radix4_lanes(float (&zr)[8], float (&zi)[8], int lane) {
    const float E = (float)SIGN;
    float s16 = (lane & 16) ? -1.0f : 1.0f;
    float s8  = (lane & 8)  ? -1.0f : 1.0f;
    bool tw = ((lane & 24) == 24);
#pragma unroll
    for (int r = 0; r < 8; r++) {
        float pr = __shfl_xor_sync(0xffffffffu, zr[r], 16);
        float pi = __shfl_xor_sync(0xffffffffu, zi[r], 16);
        float ar = fmaf(s16, zr[r], pr);
        float ai = fmaf(s16, zi[r], pi);
        if (tw) { float tt = ar; ar = -E * ai; ai = E * tt; }   // * (0,E)
        float qr = __shfl_xor_sync(0xffffffffu, ar, 8);
        float qi = __shfl_xor_sync(0xffffffffu, ai, 8);
        zr[r] = fmaf(s8, ar, qr);
        zi[r] = fmaf(s8, ai, qi);
    }
}

__device__ __constant__ int BRC[8] = {0, 4, 2, 6, 1, 5, 3, 7};

// full 256-pt FFT: input vr[j] = x[lane + 32*j]; scratch = 256-float swizzled
// warp-private region (indexed SADDR(row)); output vr[j] = X[n],
// n = (lane&7) + 8*e0(lane) + 32*brev3(j). e0(lane) = bit4 + 2*bit3.
#define FFT256(SIGN, vr, vi, SADDR_R, SADDR_W, t1r, t1i, t2r, t2i)                 \
    {                                                                              \
        radix8<SIGN>(vr, vi);                                                      \
        _Pragma("unroll")                                                          \
        for (int j = 0; j < 8; j++) {                                              \
            int c = BRC[j];                                                        \
            float wr = t1r[c * 32 + lane], wi = t1i[c * 32 + lane];                \
            float nr = vr[j] * wr - vi[j] * wi;                                    \
            float ni = vr[j] * wi + vi[j] * wr;                                    \
            int row = lane + 32 * c;                                               \
            SADDR_W(row, nr, ni);                                                  \
        }                                                                          \
        __syncwarp();                                                              \
        _Pragma("unroll")                                                          \
        for (int r = 0; r < 8; r++) {                                              \
            int row = r + 8 * (lane >> 3) + 32 * (lane & 7);                       \
            SADDR_R(row, vr[r], vi[r]);                                            \
        }                                                                          \
        radix4_lanes<SIGN>(vr, vi, lane);                                          \
        _Pragma("unroll")                                                          \
        for (int r = 0; r < 8; r++) {                                              \
            float wr = t2r[r * 32 + lane], wi = t2i[r * 32 + lane];                \
            float nr = vr[r] * wr - vi[r] * wi;                                    \
            float ni = vr[r] * wi + vi[r] * wr;                                    \
            vr[r] = nr; vi[r] = ni;                                                \
        }                                                                          \
        radix8<SIGN>(vr, vi);                                                      \
    }

// ---------------- row forward FFT + prob2-table CTAs ----------------
__global__ void k_row_fwd(const float* __restrict__ x, float* __restrict__ fftreg,
                          const float* __restrict__ w) {
    if (blockIdx.x == HH / 8) {
        int idx0 = blockIdx.y * 1024 + threadIdx.x * 4;
        float4 wq = *reinterpret_cast<const float4*>(w + idx0);
        float rr = g_r, bb = g_beta;
        int le = g_le;
        float pv[4] = {wq.x, wq.y, wq.z, wq.w};
        float res[4];
#pragma unroll
        for (int j = 0; j < 4; j++) {
            float p1 = prob1_of(pv[j]);
            res[j] = le ? __fmul_rn(p1, rr)
                        : __fsub_rn(1.0f, __fmul_rn(__fsub_rn(1.0f, p1), bb));
        }
        *reinterpret_cast<float4*>(g_prob2 + idx0) = make_float4(res[0], res[1], res[2], res[3]);
        return;
    }
    __shared__ float scr[8][512];   // per-warp: [0..255]=re, [256..511]=im
    __shared__ float t1r[256], t1i[256], t2r[256], t2i[256];
    int t = threadIdx.x, lane = t & 31, wp = t >> 5;
    t1r[t] = g_t1r_f[t]; t1i[t] = g_t1i_f[t];
    t2r[t] = g_t2r_f[t]; t2i[t] = g_t2i_f[t];
    __syncthreads();
    int row = blockIdx.x * 8 + wp, b = blockIdx.y;
    const float* xp = x + (size_t)b * HWSZ + (size_t)row * WW;
    float* sc = scr[wp];
    float vr[8], vi[8];
#pragma unroll
    for (int j = 0; j < 8; j++) { vr[j] = xp[lane + 32 * j]; vi[j] = 0.0f; }
#define RW_W(rw, nr, ni) { sc[SWZ(rw)] = nr; sc[256 + SWZ(rw)] = ni; }
#define RW_R(rw, or_, oi_) { or_ = sc[SWZ(rw)]; oi_ = sc[256 + SWZ(rw)]; }
    FFT256(-1, vr, vi, RW_R, RW_W, t1r, t1i, t2r, t2i);
    int d0l = ((lane >> 4) & 1) + (((lane >> 3) & 1) << 1);
    float* fr = fftreg + (size_t)b * 2 * HWSZ + (size_t)row * WW;
    float* fi = fr + HWSZ;
#pragma unroll
    for (int j = 0; j < 8; j++) {
        int n = (lane & 7) + 8 * d0l + 32 * BRC[j];   // one 128B line per j
        fr[n] = vr[j]; fi[n] = vi[j];
    }
#undef RW_W
#undef RW_R
}

// ---------- fused column kernel: 32-col tile, 512 threads ----------
#define CCP 288
#define SMADDR(col, row) ((col) * CCP + (SWZ(row) ^ ((((col) >> 2) & 7) << 2)))

__global__ void __launch_bounds__(512, 2)
k_col(float* __restrict__ fftreg, float* __restrict__ maskreg,
      float* __restrict__ ukreg, float* __restrict__ stage,
      unsigned sk0, unsigned sk1) {
    extern __shared__ float sm[];
    float* sre = sm;
    float* sim = sm + 32 * CCP;
    float* tw = sm + 64 * CCP;
    float* t1r_f = tw;        float* t1i_f = tw + 256;
    float* t2r_f = tw + 512;  float* t2i_f = tw + 768;
    float* t1r_i = tw + 1024; float* t1i_i = tw + 1280;
    float* t2r_i = tw + 1536; float* t2i_i = tw + 1792;
    int t = threadIdx.x, lane = t & 31, wp = t >> 5;   // wp 0..15
    int b = blockIdx.y, c0 = blockIdx.x * 32;
    int cg = t & 7, rloc = t >> 3;                     // rloc 0..63
    float* fr = fftreg + (size_t)b * 2 * HWSZ;
    float* fi = fr + HWSZ;

    if (t < 256) {
        t1r_f[t] = g_t1r_f[t]; t1i_f[t] = g_t1i_f[t];
        t2r_f[t] = g_t2r_f[t]; t2i_f[t] = g_t2i_f[t];
        t1r_i[t] = g_t1r_i[t]; t1i_i[t] = g_t1i_i[t];
        t2r_i[t] = g_t2r_i[t]; t2i_i[t] = g_t2i_i[t];
    }

    // load 256x32 tile, float4 (fully coalesced), natural rows
#pragma unroll
    for (int k = 0; k < 4; k++) {
        int row = k * 64 + rloc;
        int g = row * WW + c0 + cg * 4;
        float4 vre = *reinterpret_cast<const float4*>(fr + g);
        float4 vim = *reinterpret_cast<const float4*>(fi + g);
        int c = cg * 4;
        sre[SMADDR(c, row)] = vre.x;     sim[SMADDR(c, row)] = vim.x;
        sre[SMADDR(c + 1, row)] = vre.y; sim[SMADDR(c + 1, row)] = vim.y;
        sre[SMADDR(c + 2, row)] = vre.z; sim[SMADDR(c + 2, row)] = vim.z;
        sre[SMADDR(c + 3, row)] = vre.w; sim[SMADDR(c + 3, row)] = vim.w;
    }
    __syncthreads();

#define CW_W(rw, nr, ni) { sre[SMADDR(cc, rw)] = nr; sim[SMADDR(cc, rw)] = ni; }
#define CW_R(rw, or_, oi_) { or_ = sre[SMADDR(cc, rw)]; oi_ = sim[SMADDR(cc, rw)]; }
    // forward FFTs: 2 columns per warp, natural-order output rows
    int d0l = ((lane >> 4) & 1) + (((lane >> 3) & 1) << 1);
#pragma unroll 1
    for (int j2 = 0; j2 < 2; j2++) {
        int cc = wp * 2 + j2;
        float vr[8], vi[8];
#pragma unroll
        for (int j = 0; j < 8; j++) {
            int row = lane + 32 * j;
            vr[j] = sre[SMADDR(cc, row)]; vi[j] = sim[SMADDR(cc, row)];
        }
        FFT256(-1, vr, vi, CW_R, CW_W, t1r_f, t1i_f, t2r_f, t2i_f);
        __syncwarp();
#pragma unroll
        for (int j = 0; j < 8; j++) {
            int row = (lane & 7) + 8 * d0l + 32 * BRC[j];
            sre[SMADDR(cc, row)] = vr[j]; sim[SMADDR(cc, row)] = vi[j];
        }
        __syncwarp();
    }
    __syncthreads();

    // outputs: fft, mask (threefry), u_k (float4); stash u_k back in smem
    float* ur = ukreg + (size_t)b * 2 * HWSZ;
    float* ui = ur + HWSZ;
    float* mk = maskreg + (size_t)b * HWSZ;
#pragma unroll 1
    for (int k = 0; k < 4; k++) {
        int row = k * 64 + rloc;
        int g = row * WW + c0 + cg * 4;
        int c = cg * 4;
        float xr[4], xi[4], mm[4];
        unsigned base = (unsigned)(b * HWSZ + g);
        float4 p2 = *reinterpret_cast<const float4*>(g_prob2 + g);
        float pv[4] = {p2.x, p2.y, p2.z, p2.w};
#pragma unroll
        for (int q = 0; q < 4; q++) {
            xr[q] = sre[SMADDR(c + q, row)];
            xi[q] = sim[SMADDR(c + q, row)];
            unsigned o0, o1;
            threefry2x32(sk0, sk1, 0u, base + (unsigned)q, o0, o1);
            unsigned bits = o0 ^ o1;
            float u = __uint_as_float((bits >> 9) | 0x3f800000u) - 1.0f;
            mm[q] = (pv[q] > u) ? 1.0f : 0.0f;
        }
        *reinterpret_cast<float4*>(fr + g) = make_float4(xr[0], xr[1], xr[2], xr[3]);
        *reinterpret_cast<float4*>(fi + g) = make_float4(xi[0], xi[1], xi[2], xi[3]);
        *reinterpret_cast<float4*>(mk + g) = make_float4(mm[0], mm[1], mm[2], mm[3]);
        float kr[4], ki[4];
#pragma unroll
        for (int q = 0; q < 4; q++) {
            kr[q] = xr[q] * mm[q]; ki[q] = xi[q] * mm[q];
            sre[SMADDR(c + q, row)] = kr[q];
            sim[SMADDR(c + q, row)] = ki[q];
        }
        *reinterpret_cast<float4*>(ur + g) = make_float4(kr[0], kr[1], kr[2], kr[3]);
        *reinterpret_cast<float4*>(ui + g) = make_float4(ki[0], ki[1], ki[2], ki[3]);
    }
    __syncthreads();

    // inverse FFTs: 2 columns per warp (1/256 folded into t2_i)
#pragma unroll 1
    for (int j2 = 0; j2 < 2; j2++) {
        int cc = wp * 2 + j2;
        float vr[8], vi[8];
#pragma unroll
        for (int j = 0; j < 8; j++) {
            int row = lane + 32 * j;
            vr[j] = sre[SMADDR(cc, row)]; vi[j] = sim[SMADDR(cc, row)];
        }
        FFT256(1, vr, vi, CW_R, CW_W, t1r_i, t1i_i, t2r_i, t2i_i);
        __syncwarp();
#pragma unroll
        for (int j = 0; j < 8; j++) {
            int row = (lane & 7) + 8 * d0l + 32 * BRC[j];
            sre[SMADDR(cc, row)] = vr[j]; sim[SMADDR(cc, row)] = vi[j];
        }
        __syncwarp();
    }
    __syncthreads();
#undef CW_W
#undef CW_R

    // store to staging (uifft region), float4
    float* dr = stage + (size_t)b * 2 * HWSZ;
    float* di = dr + HWSZ;
#pragma unroll
    for (int k = 0; k < 4; k++) {
        int row = k * 64 + rloc;
        int g = row * WW + c0 + cg * 4;
        int c = cg * 4;
        float4 vre, vim;
        vre.x = sre[SMADDR(c, row)];     vim.x = sim[SMADDR(c, row)];
        vre.y = sre[SMADDR(c + 1, row)]; vim.y = sim[SMADDR(c + 1, row)];
        vre.z = sre[SMADDR(c + 2, row)]; vim.z = sim[SMADDR(c + 2, row)];
        vre.w = sre[SMADDR(c + 3, row)]; vim.w = sim[SMADDR(c + 3, row)];
        *reinterpret_cast<float4*>(dr + g) = vre;
        *reinterpret_cast<float4*>(di + g) = vim;
    }
}

// ---------- row inverse FFT (in place on uifft) + complex abs ----------
__global__ void k_row_inv(float* __restrict__ uifft, float* __restrict__ cabs) {
    __shared__ float scr[8][512];
    __shared__ float t1r[256], t1i[256], t2r[256], t2i[256];
    int t = threadIdx.x, lane = t & 31, wp = t >> 5;
    t1r[t] = g_t1r_i[t]; t1i[t] = g_t1i_i[t];
    t2r[t] = g_t2r_i[t]; t2i[t] = g_t2i_i[t];
    __syncthreads();
    int row = blockIdx.x * 8 + wp, b = blockIdx.y;
    float* fr = uifft + (size_t)b * 2 * HWSZ + (size_t)row * WW;
    float* fi = fr + HWSZ;
    float* sc = scr[wp];
    float vr[8], vi[8];
#pragma unroll
    for (int j = 0; j < 8; j++) { vr[j] = fr[lane + 32 * j]; vi[j] = fi[lane + 32 * j]; }
#define RW_W(rw, nr, ni) { sc[SWZ(rw)] = nr; sc[256 + SWZ(rw)] = ni; }
#define RW_R(rw, or_, oi_) { or_ = sc[SWZ(rw)]; oi_ = sc[256 + SWZ(rw)]; }
    FFT256(1, vr, vi, RW_R, RW_W, t1r, t1i, t2r, t2i);
    int d0l = ((lane >> 4) & 1) + (((lane >> 3) & 1) << 1);
    float* ap = cabs + (size_t)b * HWSZ + (size_t)row * WW;
#pragma unroll
    for (int j = 0; j < 8; j++) {
        int n = (lane & 7) + 8 * d0l + 32 * BRC[j];   // one 128B line per j
        fr[n] = vr[j]; fi[n] = vi[j];
        ap[n] = sqrtf(vr[j] * vr[j] + vi[j] * vi[j]);
    }
#undef RW_W
#undef RW_R
}

extern "C" void kernel_launch(void* const* d_in, const int* in_sizes, int n_in,
                              void* d_out, int out_size) {
    const float* x = (const float*)d_in[0];
    const float* w = (const float*)d_in[1];
    if (n_in >= 2 && in_sizes[0] == HWSZ) {
        x = (const float*)d_in[1];
        w = (const float*)d_in[0];
    }
    float* out   = (float*)d_out;
    float* uifft = out + OFF_UIFFT;
    float* cabs  = out + OFF_ABS;
    float* mask  = out + OFF_MASK;
    float* fft   = out + OFF_FFT;
    float* uk    = out + OFF_UK;

    unsigned sk0, sk1;
    threefry2x32(0u, 42u, 0u, 1u, sk0, sk1);

    const int col_smem = (2 * 32 * CCP + 8 * 256) * (int)sizeof(float);   // 81920
    static int smem_set = 0;
    if (!smem_set) {
        cudaFuncSetAttribute(k_col, cudaFuncAttributeMaxDynamicSharedMemorySize, col_smem);
        smem_set = 1;
    }

    k_reduce<<<64, 256>>>(w);
    k_final<<<1, 256>>>();
    k_row_fwd<<<dim3(HH / 8 + 1, BB), 256>>>(x, fft, w);
    k_col<<<dim3(WW / 32, BB), 512, col_smem>>>(fft, mask, uk, uifft, sk0, sk1);
    k_row_inv<<<dim3(HH / 8, BB), 256>>>(uifft, cabs);
}